// round 12
// baseline (speedup 1.0000x reference)
#include <cuda_runtime.h>
#include <cuda_fp16.h>
#include <mma.h>
#include <cstddef>
#include <cstdint>

using namespace nvcuda;

#define V    6912
#define G4   27648   // 4*V
#define BSZ  16
#define TT   8
#define TR   4

// ---------------- device scratch (no allocation allowed) ----------------
// Gate-interleaved layouts: index n' = j*4 + g  (g: 0=i,1=f,2=g,3=o)
__device__ __half g_whh16[(size_t)G4 * V];   // fp16 W_hh_enc, rows interleaved
__device__ __half g_x16 [128 * V];           // x fp16
__device__ __half g_h16 [2][BSZ * V];        // encoder h fp16, ping-pong
__device__ __half g_hd16[BSZ * TR * V];      // decoder h_d (fp16, GEMM A)
__device__ float  g_h   [BSZ * V];           // encoder h fp32 (fc_enc)
__device__ float  g_c   [BSZ * V];
__device__ float  g_xg  [128 * G4];          // xg, cols interleaved
__device__ float  g_dec [BSZ * TR * V];      // fc_dec accumulator (atomic)
__device__ float  g_bep [G4];                // b_enc permuted
__device__ float  g_bdp [G4];                // b_dec permuted
__device__ float  g_widp[G4];                // W_ih_dec permuted

__device__ __forceinline__ float sigf(float x) { return 1.0f / (1.0f + expf(-x)); }

__device__ __forceinline__ uint4 pack8(float4 a, float4 b)
{
    __half2 h0 = __floats2half2_rn(a.x, a.y);
    __half2 h1 = __floats2half2_rn(a.z, a.w);
    __half2 h2 = __floats2half2_rn(b.x, b.y);
    __half2 h3 = __floats2half2_rn(b.z, b.w);
    uint4 u;
    u.x = *reinterpret_cast<unsigned*>(&h0);
    u.y = *reinterpret_cast<unsigned*>(&h1);
    u.z = *reinterpret_cast<unsigned*>(&h2);
    u.w = *reinterpret_cast<unsigned*>(&h3);
    return u;
}

// =====================================================================
// Combined prologue: blocks [0,432): x -> fp16; [432,540): permute b/W vecs
// =====================================================================
__global__ void prep_conv_kernel(const float* __restrict__ x,
                                 const float* __restrict__ be,
                                 const float* __restrict__ bd,
                                 const float* __restrict__ wid)
{
    int bx = blockIdx.x;
    if (bx < 432) {
        int idx = bx * 256 + threadIdx.x;           // 432*256 = 128*V/8
        const float4* s = (const float4*)x + (size_t)idx * 2;
        ((uint4*)g_x16)[idx] = pack8(s[0], s[1]);
    } else {
        int idx = (bx - 432) * 256 + threadIdx.x;   // 108*256 = G4
        int src = (idx & 3) * V + (idx >> 2);
        g_bep[idx]  = be[src];
        g_bdp[idx]  = bd[src];
        g_widp[idx] = wid[src];
    }
}

// =====================================================================
// xg GEMM: BM=64 (grid.y = m-half), BN=128, BK=64, full K, direct store,
// fused step-0 gate epilogue (h0 = c0 = 0 path).
// =====================================================================
__global__ __launch_bounds__(256) void gemm_xg_kernel(const float* __restrict__ Wih)
{
    constexpr int BK = 64, BNB = 128, LDS = BK + 8;
    __shared__ __align__(16) __half sA[2][64][LDS];
    __shared__ __align__(16) __half sB[2][BNB][LDS];

    const int tid = threadIdx.x;
    const int n0  = blockIdx.x * BNB;
    const int z   = blockIdx.y;
    const int m0  = z * 64;

    const int w  = tid >> 5;
    const int wm = w >> 2, wn = w & 3;          // 2 x 4 warps, WM=32, WN=32

    wmma::fragment<wmma::accumulator, 16, 16, 16, float> acc[2][2];
#pragma unroll
    for (int i = 0; i < 2; i++)
#pragma unroll
        for (int j = 0; j < 2; j++) wmma::fill_fragment(acc[i][j], 0.0f);

    uint4 rb[4], ra[2];
    auto load = [&](int k0) {
#pragma unroll
        for (int p = 0; p < 4; p++) {               // B: 128 rows x 8 chunks
            int c = tid + p * 256;
            int row = c >> 3, kc = (c & 7) * 8;
            int nn = n0 + row;
            const float* s = Wih + ((size_t)(nn & 3) * V + (nn >> 2)) * V + k0 + kc;
            rb[p] = pack8(*(const float4*)s, *(const float4*)(s + 4));
        }
#pragma unroll
        for (int p = 0; p < 2; p++) {               // A: 64 rows x 8 chunks
            int c = tid + p * 256;
            int row = c >> 3, kc = (c & 7) * 8;
            ra[p] = *(const uint4*)(g_x16 + (size_t)(m0 + row) * V + k0 + kc);
        }
    };
    auto store = [&](int buf) {
#pragma unroll
        for (int p = 0; p < 4; p++) {
            int c = tid + p * 256;
            int row = c >> 3, kc = (c & 7) * 8;
            *(uint4*)(&sB[buf][row][kc]) = rb[p];
        }
#pragma unroll
        for (int p = 0; p < 2; p++) {
            int c = tid + p * 256;
            int row = c >> 3, kc = (c & 7) * 8;
            *(uint4*)(&sA[buf][row][kc]) = ra[p];
        }
    };

    load(0);
    store(0);
    load(BK);
    __syncthreads();

    const int niter = V / BK;   // 108
    for (int i = 0; i < niter; i++) {
        int p = i & 1;
        if (i + 1 < niter) store(p ^ 1);
        if (i + 2 < niter) load((i + 2) * BK);
#pragma unroll
        for (int kk = 0; kk < BK; kk += 16) {
            wmma::fragment<wmma::matrix_a, 16, 16, 16, __half, wmma::row_major> af[2];
            wmma::fragment<wmma::matrix_b, 16, 16, 16, __half, wmma::col_major> bf[2];
#pragma unroll
            for (int i_ = 0; i_ < 2; i_++)
                wmma::load_matrix_sync(af[i_], &sA[p][wm * 32 + i_ * 16][kk], LDS);
#pragma unroll
            for (int j_ = 0; j_ < 2; j_++)
                wmma::load_matrix_sync(bf[j_], &sB[p][wn * 32 + j_ * 16][kk], LDS);
#pragma unroll
            for (int i_ = 0; i_ < 2; i_++)
#pragma unroll
                for (int j_ = 0; j_ < 2; j_++)
                    wmma::mma_sync(acc[i_][j_], af[i_], bf[j_], acc[i_][j_]);
        }
        __syncthreads();
    }

#pragma unroll
    for (int i_ = 0; i_ < 2; i_++)
#pragma unroll
        for (int j_ = 0; j_ < 2; j_++)
            wmma::store_matrix_sync(
                g_xg + (size_t)(m0 + wm * 32 + i_ * 16) * G4 + n0 + wn * 32 + j_ * 16,
                acc[i_][j_], G4, wmma::mem_row_major);
    __syncthreads();   // block-local visibility of this block's xg stores

    // fused step-0: rows m=b*8 for b = z*8..z*8+7 and columns jg*4 in tile
    {
        int b  = z * 8 + (tid >> 5);
        int jg = blockIdx.x * 32 + (tid & 31);
        float4 x4 = *(const float4*)&g_xg[(size_t)(b * 8) * G4 + (size_t)jg * 4];
        float4 bb = *(const float4*)&g_bep[jg * 4];
        float i_ = sigf (x4.x + bb.x);
        float gg = tanhf(x4.z + bb.z);
        float o_ = sigf (x4.w + bb.w);
        float c  = i_ * gg;
        int idx = b * V + jg;
        g_c[idx] = c;
        float h  = o_ * tanhf(c);
        g_h[idx]      = h;
        g_h16[0][idx] = __float2half(h);
    }
}

// =====================================================================
// Shared epilogue pieces
// =====================================================================
__device__ __forceinline__ void combine8(float (*sR)[16][32], float (*sF)[64])
{
    int tid = threadIdx.x;
    for (int c = tid; c < 16 * 64; c += 256) {
        int m = c >> 6, n = c & 63;
        int f = n >> 4, cc = n & 15;
        sF[m][n] = sR[f][m][cc] + sR[f + 4][m][cc];
    }
}

__device__ __forceinline__ void enc_epilogue(float (*sF)[64], int jbase, int t,
                                             __half* __restrict__ hout)
{
    int tid = threadIdx.x;
    int b = tid >> 4, jl = tid & 15;
    int jg = jbase + jl;
    float4 pre = *(float4*)&sF[b][jl * 4];
    float4 xg4 = *(const float4*)&g_xg[(size_t)(b * 8 + t) * G4 + (size_t)jg * 4];
    float4 bb  = *(const float4*)&g_bep[jg * 4];
    float i_ = sigf (pre.x + xg4.x + bb.x);
    float f_ = sigf (pre.y + xg4.y + bb.y);
    float gg = tanhf(pre.z + xg4.z + bb.z);
    float o_ = sigf (pre.w + xg4.w + bb.w);
    int idx = b * V + jg;
    float c = f_ * g_c[idx] + i_ * gg;
    g_c[idx] = c;
    float h = o_ * tanhf(c);
    g_h[idx]  = h;
    hout[idx] = __float2half(h);
}

__device__ __forceinline__ void dec_epilogue(float (*sF)[64], int jbase,
                                             const float* __restrict__ xrev)
{
    int tid = threadIdx.x;
    int b = tid >> 4, jl = tid & 15;
    int jg = jbase + jl;
    float4 pre = *(float4*)&sF[b][jl * 4];
    float4 bb  = *(const float4*)&g_bdp[jg * 4];
    float4 ww  = *(const float4*)&g_widp[jg * 4];
    float bi = pre.x + bb.x, bf_ = pre.y + bb.y;
    float bg = pre.z + bb.z, bo = pre.w + bb.w;
    float ce = g_c[b * V + jg];
#pragma unroll
    for (int tr = 0; tr < TR; tr++) {
        float xr = xrev[b * TR + tr];
        float i_ = sigf (bi + xr * ww.x);
        float f_ = sigf (bf_ + xr * ww.y);
        float gg = tanhf(bg + xr * ww.z);
        float o_ = sigf (bo + xr * ww.w);
        float cd = f_ * ce + i_ * gg;
        size_t o = (size_t)(b * TR + tr) * V + jg;
        g_hd16[o] = __float2half(o_ * tanhf(cd));
        g_dec[o]  = 0.f;                 // pre-zero for fc_dec atomics
    }
}

// =====================================================================
// Fused recurrence step, fp16 interleaved weights (steps 2..7).
// BK=128, 3 stages, all 8 warps compute every iteration (K-half split).
// =====================================================================
__global__ __launch_bounds__(256) void rec_ca_kernel(int t)
{
    constexpr int BK = 128, STAGES = 3, BNN = 64, LDS = BK + 8;
    union SM {
        struct { __half A[STAGES][16][LDS]; __half B[STAGES][BNN][LDS]; } st;
        struct { float R[8][16][32]; float F[16][64]; } ep;
    };
    __shared__ __align__(16) SM sm;

    const __half* hin  = g_h16[(t + 1) & 1];
    __half*       hout = g_h16[t & 1];

    const int tid = threadIdx.x;
    const int w   = tid >> 5;
    const int nf  = w & 3;
    const int kh  = w >> 2;
    const int n0  = blockIdx.x * BNN;
    const int niter = V / BK;   // 54

    wmma::fragment<wmma::accumulator, 16, 16, 16, float> acc;
    wmma::fill_fragment(acc, 0.0f);

    auto stage = [&](int s, int k0) {
#pragma unroll
        for (int p = 0; p < 4; p++) {               // B: 64 rows x 16 chunks
            int c = tid + p * 256;
            int row = c >> 4, kc = (c & 15) * 8;
            uint32_t d = (uint32_t)__cvta_generic_to_shared(&sm.st.B[s][row][kc]);
            const void* g = g_whh16 + (size_t)(n0 + row) * V + k0 + kc;
            asm volatile("cp.async.cg.shared.global [%0], [%1], 16;\n" :: "r"(d), "l"(g));
        }
        {                                           // A: 16 rows x 16 chunks
            int row = tid >> 4, kc = (tid & 15) * 8;
            uint32_t d = (uint32_t)__cvta_generic_to_shared(&sm.st.A[s][row][kc]);
            const void* g = hin + (size_t)row * V + k0 + kc;
            asm volatile("cp.async.cg.shared.global [%0], [%1], 16;\n" :: "r"(d), "l"(g));
        }
        asm volatile("cp.async.commit_group;\n");
    };

    int issued = 0;
    for (; issued < STAGES - 1; issued++) stage(issued, issued * BK);

    for (int i = 0; i < niter; i++) {
        if (issued < niter) { stage(issued % STAGES, issued * BK); issued++; }
        else                { asm volatile("cp.async.commit_group;\n"); }
        asm volatile("cp.async.wait_group %0;\n" :: "n"(STAGES - 1));
        __syncthreads();
        int s = i % STAGES;
        int kb = kh * 64;
#pragma unroll
        for (int kk = kb; kk < kb + 64; kk += 16) {
            wmma::fragment<wmma::matrix_a, 16, 16, 16, __half, wmma::row_major> af;
            wmma::fragment<wmma::matrix_b, 16, 16, 16, __half, wmma::col_major> bf;
            wmma::load_matrix_sync(af, &sm.st.A[s][0][kk], LDS);
            wmma::load_matrix_sync(bf, &sm.st.B[s][nf * 16][kk], LDS);
            wmma::mma_sync(acc, af, bf, acc);
        }
        __syncthreads();
    }

    wmma::store_matrix_sync(&sm.ep.R[w][0][0], acc, 32, wmma::mem_row_major);
    __syncthreads();
    combine8(sm.ep.R, sm.ep.F);
    __syncthreads();
    enc_epilogue(sm.ep.F, blockIdx.x * 16, t, hout);
}

// =====================================================================
// Fused recurrence/decoder step, fp32 weights, gate-interleave perm +
// in-register fp16 convert.  BK=128, 2-stage register pipeline, all 8
// warps compute every iteration.  WRITEB: persist fp16 copy.
// =====================================================================
template<bool WRITEB, bool DEC>
__global__ __launch_bounds__(256) void rec_f32_kernel(
    const float* __restrict__ W, int t, const float* __restrict__ xrev)
{
    constexpr int BK = 128, BNN = 64, LDS = BK + 8;
    union SM {
        struct { __half A[2][16][LDS]; __half B[2][BNN][LDS]; } st;
        struct { float R[8][16][32]; float F[16][64]; } ep;
    };
    __shared__ __align__(16) SM sm;

    const __half* hin  = g_h16[(t + 1) & 1];
    __half*       hout = g_h16[t & 1];

    const int tid = threadIdx.x;
    const int w   = tid >> 5;
    const int nf  = w & 3;
    const int kh  = w >> 2;
    const int n0  = blockIdx.x * BNN;
    const int niter = V / BK;   // 54

    wmma::fragment<wmma::accumulator, 16, 16, 16, float> acc;
    wmma::fill_fragment(acc, 0.0f);

    uint4 rb[4], ra;
    auto load = [&](int k0) {
#pragma unroll
        for (int p = 0; p < 4; p++) {               // B: 64 rows x 16 chunks
            int c = tid + p * 256;
            int row = c >> 4, kc = (c & 15) * 8;
            int nn = n0 + row;
            const float* s = W + ((size_t)(nn & 3) * V + (nn >> 2)) * V + k0 + kc;
            rb[p] = pack8(*(const float4*)s, *(const float4*)(s + 4));
            if constexpr (WRITEB)
                *(uint4*)(g_whh16 + (size_t)nn * V + k0 + kc) = rb[p];
        }
        {                                           // A: 16 rows x 16 chunks
            int row = tid >> 4, kc = (tid & 15) * 8;
            ra = *(const uint4*)(hin + (size_t)row * V + k0 + kc);
        }
    };
    auto store = [&](int buf) {
#pragma unroll
        for (int p = 0; p < 4; p++) {
            int c = tid + p * 256;
            int row = c >> 4, kc = (c & 15) * 8;
            *(uint4*)(&sm.st.B[buf][row][kc]) = rb[p];
        }
        *(uint4*)(&sm.st.A[buf][tid >> 4][(tid & 15) * 8]) = ra;
    };

    load(0);
    store(0);
    load(BK);
    __syncthreads();

    for (int i = 0; i < niter; i++) {
        int p = i & 1;
        if (i + 1 < niter) store(p ^ 1);
        if (i + 2 < niter) load((i + 2) * BK);
        int kb = kh * 64;
#pragma unroll
        for (int kk = kb; kk < kb + 64; kk += 16) {
            wmma::fragment<wmma::matrix_a, 16, 16, 16, __half, wmma::row_major> af;
            wmma::fragment<wmma::matrix_b, 16, 16, 16, __half, wmma::col_major> bf;
            wmma::load_matrix_sync(af, &sm.st.A[p][0][kk], LDS);
            wmma::load_matrix_sync(bf, &sm.st.B[p][nf * 16][kk], LDS);
            wmma::mma_sync(acc, af, bf, acc);
        }
        __syncthreads();
    }

    wmma::store_matrix_sync(&sm.ep.R[w][0][0], acc, 32, wmma::mem_row_major);
    __syncthreads();
    combine8(sm.ep.R, sm.ep.F);
    __syncthreads();
    if constexpr (DEC) dec_epilogue(sm.ep.F, blockIdx.x * 16, xrev);
    else               enc_epilogue(sm.ep.F, blockIdx.x * 16, t, hout);
}

// =====================================================================
__global__ void fc_enc_kernel(const float* __restrict__ wgt,
                              const float* __restrict__ bias,
                              float* __restrict__ out)
{
    __shared__ float red[256];
    int b = blockIdx.x;
    const float* h = g_h + (size_t)b * V;
    float s = 0.0f;
    for (int k = threadIdx.x; k < V; k += 256) s = fmaf(h[k], wgt[k], s);
    red[threadIdx.x] = s;
    __syncthreads();
    for (int st = 128; st > 0; st >>= 1) {
        if (threadIdx.x < st) red[threadIdx.x] += red[threadIdx.x + st];
        __syncthreads();
    }
    if (threadIdx.x == 0) out[b] = red[0] + bias[0];
}

// =====================================================================
// fc_dec GEMM: BM=64 rows of hd, K-split 4, atomic-reduce into g_dec.
// =====================================================================
__global__ __launch_bounds__(256)
void gemm_fcdec(const __half* __restrict__ A, const float* __restrict__ Bf,
                float* __restrict__ C, int N, int klen)
{
    constexpr int BM = 64, BK = 32, BNB = 128, LDS = BK + 8;
    __shared__ __align__(16) __half sA[2][BM][LDS];
    __shared__ __align__(16) __half sB[2][BNB][LDS];
    __shared__ __align__(16) float  sC[BM][BNB + 4];

    const int tid   = threadIdx.x;
    const int n0    = blockIdx.x * BNB;
    const int kbase = blockIdx.y * klen;
    const int niter = klen / BK;

    const int w  = tid >> 5;
    const int wm = w >> 2, wn = w & 3;

    wmma::fragment<wmma::accumulator, 16, 16, 16, float> acc[2][2];
#pragma unroll
    for (int i = 0; i < 2; i++)
#pragma unroll
        for (int j = 0; j < 2; j++) wmma::fill_fragment(acc[i][j], 0.0f);

    uint4 rb[2], ra;
    auto load = [&](int k0) {
#pragma unroll
        for (int p = 0; p < 2; p++) {
            int c = tid + p * 256;
            int row = c >> 2, kc = (c & 3) * 8;
            const float* s = Bf + (size_t)(n0 + row) * V + k0 + kc;
            rb[p] = pack8(*(const float4*)s, *(const float4*)(s + 4));
        }
        ra = *(const uint4*)(A + (size_t)(tid >> 2) * V + k0 + (tid & 3) * 8);
    };
    auto store = [&](int buf) {
#pragma unroll
        for (int p = 0; p < 2; p++) {
            int c = tid + p * 256;
            int row = c >> 2, kc = (c & 3) * 8;
            *(uint4*)(&sB[buf][row][kc]) = rb[p];
        }
        *(uint4*)(&sA[buf][tid >> 2][(tid & 3) * 8]) = ra;
    };

    load(kbase);
    store(0);
    if (niter > 1) load(kbase + BK);
    __syncthreads();

    for (int i = 0; i < niter; i++) {
        int p = i & 1;
        if (i + 1 < niter) store(p ^ 1);
        if (i + 2 < niter) load(kbase + (i + 2) * BK);
#pragma unroll
        for (int kk = 0; kk < BK; kk += 16) {
            wmma::fragment<wmma::matrix_a, 16, 16, 16, __half, wmma::row_major> af[2];
            wmma::fragment<wmma::matrix_b, 16, 16, 16, __half, wmma::col_major> bf[2];
#pragma unroll
            for (int i_ = 0; i_ < 2; i_++)
                wmma::load_matrix_sync(af[i_], &sA[p][wm * 32 + i_ * 16][kk], LDS);
#pragma unroll
            for (int j_ = 0; j_ < 2; j_++)
                wmma::load_matrix_sync(bf[j_], &sB[p][wn * 32 + j_ * 16][kk], LDS);
#pragma unroll
            for (int i_ = 0; i_ < 2; i_++)
#pragma unroll
                for (int j_ = 0; j_ < 2; j_++)
                    wmma::mma_sync(acc[i_][j_], af[i_], bf[j_], acc[i_][j_]);
        }
        __syncthreads();
    }

#pragma unroll
    for (int i_ = 0; i_ < 2; i_++)
#pragma unroll
        for (int j_ = 0; j_ < 2; j_++)
            wmma::store_matrix_sync(&sC[wm * 32 + i_ * 16][wn * 32 + j_ * 16],
                                    acc[i_][j_], BNB + 4, wmma::mem_row_major);
    __syncthreads();
    for (int c = tid; c < BM * BNB; c += 256) {
        int m = c / BNB, n = c - m * BNB;
        atomicAdd(&C[(size_t)m * N + n0 + n], sC[m][n]);
    }
}

// =====================================================================
__global__ void dec_out_kernel(const float* __restrict__ fcb,
                               float* __restrict__ out)
{
    int idx = blockIdx.x * 256 + threadIdx.x;   // 64*V exactly
    int m = idx / V, n = idx - m * V;
    float val = g_dec[idx] + fcb[n];
    int b = m >> 2, tr = m & 3;
    size_t base = 16 + (size_t)(b * 12 + tr * 3) * V + n;
    out[base]         = val;
    out[base + V]     = val;
    out[base + 2 * V] = val;
}

// =====================================================================
extern "C" void kernel_launch(void* const* d_in, const int* in_sizes, int n_in,
                              void* d_out, int out_size)
{
    (void)in_sizes; (void)n_in; (void)out_size;
    const float* x        = (const float*)d_in[0];
    const float* x_rev    = (const float*)d_in[1];
    const float* W_ih_enc = (const float*)d_in[2];
    const float* W_hh_enc = (const float*)d_in[3];
    const float* b_enc    = (const float*)d_in[4];
    const float* fc_enc_w = (const float*)d_in[5];
    const float* fc_enc_b = (const float*)d_in[6];
    const float* W_ih_dec = (const float*)d_in[7];
    const float* W_hh_dec = (const float*)d_in[8];
    const float* b_dec    = (const float*)d_in[9];
    const float* fc_dec_w = (const float*)d_in[10];
    const float* fc_dec_b = (const float*)d_in[11];
    float* out = (float*)d_out;

    __half* hd16_p; float* dec_p;
    cudaGetSymbolAddress((void**)&hd16_p, g_hd16);
    cudaGetSymbolAddress((void**)&dec_p,  g_dec);

    // 0) x -> fp16 + permuted gate vectors (one launch)
    prep_conv_kernel<<<540, 256>>>(x, b_enc, b_dec, W_ih_dec);

    // 1) xg = x @ W_ih_enc^T (BK=64, direct store) + fused step-0 gates
    gemm_xg_kernel<<<dim3(G4 / 128, 2), 256>>>(W_ih_enc);

    // 2) step 1: fused GEMM+gates; reads buf0, writes buf1; persists fp16 W
    rec_f32_kernel<true, false><<<G4 / 64, 256>>>(W_hh_enc, 1, nullptr);

    // 3) steps 2..7: fused cp.async recurrence (BK=128, all warps active)
    for (int t = 2; t < TT; t++)
        rec_ca_kernel<<<G4 / 64, 256>>>(t);

    // 4) enc_out -> d_out[0..15]
    fc_enc_kernel<<<BSZ, 256>>>(fc_enc_w, fc_enc_b, out);

    // 5) decoder: fused GEMM + all-TR gate epilogue (reads buf1; zeroes g_dec)
    rec_f32_kernel<false, true><<<G4 / 64, 256>>>(W_hh_dec, 0, x_rev);

    // 6) dec += h_d @ fc_dec_w^T (ksplit 4, atomic), bias + repeat(3) scatter
    gemm_fcdec<<<dim3(V / 128, 4), 256>>>(hd16_p, fc_dec_w, dec_p, V, V / 4);
    dec_out_kernel<<<BSZ * TR * V / 256, 256>>>(fc_dec_b, out);
}

// round 13
// speedup vs baseline: 1.0231x; 1.0231x over previous
#include <cuda_runtime.h>
#include <cuda_fp16.h>
#include <mma.h>
#include <cstddef>
#include <cstdint>

using namespace nvcuda;

#define V    6912
#define G4   27648   // 4*V
#define BSZ  16
#define TT   8
#define TR   4

// ---------------- device scratch (no allocation allowed) ----------------
// Gate-interleaved layouts: index n' = j*4 + g  (g: 0=i,1=f,2=g,3=o)
__device__ __half g_whh16[(size_t)G4 * V];   // fp16 W_hh_enc, rows interleaved
__device__ __half g_x16 [128 * V];           // x fp16
__device__ __half g_h16 [2][BSZ * V];        // encoder h fp16, ping-pong
__device__ __half g_hd16[BSZ * TR * V];      // decoder h_d (fp16, GEMM A)
__device__ float  g_h   [BSZ * V];           // encoder h fp32 (fc_enc)
__device__ float  g_c   [BSZ * V];
__device__ float  g_xg  [128 * G4];          // xg, cols interleaved
__device__ float  g_dec [BSZ * TR * V];      // fc_dec accumulator (atomic)
__device__ float  g_bep [G4];                // b_enc permuted
__device__ float  g_bdp [G4];                // b_dec permuted
__device__ float  g_widp[G4];                // W_ih_dec permuted

__device__ __forceinline__ float sigf(float x) { return 1.0f / (1.0f + expf(-x)); }

__device__ __forceinline__ uint4 pack8(float4 a, float4 b)
{
    __half2 h0 = __floats2half2_rn(a.x, a.y);
    __half2 h1 = __floats2half2_rn(a.z, a.w);
    __half2 h2 = __floats2half2_rn(b.x, b.y);
    __half2 h3 = __floats2half2_rn(b.z, b.w);
    uint4 u;
    u.x = *reinterpret_cast<unsigned*>(&h0);
    u.y = *reinterpret_cast<unsigned*>(&h1);
    u.z = *reinterpret_cast<unsigned*>(&h2);
    u.w = *reinterpret_cast<unsigned*>(&h3);
    return u;
}

// =====================================================================
// Combined prologue: blocks [0,432): x -> fp16; [432,540): permute b/W vecs
// =====================================================================
__global__ void prep_conv_kernel(const float* __restrict__ x,
                                 const float* __restrict__ be,
                                 const float* __restrict__ bd,
                                 const float* __restrict__ wid)
{
    int bx = blockIdx.x;
    if (bx < 432) {
        int idx = bx * 256 + threadIdx.x;           // 432*256 = 128*V/8
        const float4* s = (const float4*)x + (size_t)idx * 2;
        ((uint4*)g_x16)[idx] = pack8(s[0], s[1]);
    } else {
        int idx = (bx - 432) * 256 + threadIdx.x;   // 108*256 = G4
        int src = (idx & 3) * V + (idx >> 2);
        g_bep[idx]  = be[src];
        g_bdp[idx]  = bd[src];
        g_widp[idx] = wid[src];
    }
}

// =====================================================================
// xg GEMM: BM=64 (grid.y = m-half), BN=128, BK=32, full K, direct store.
// B = W_ih_enc fp32 with gate-interleave row perm, converted in-register.
// (R11 configuration — BK=64 variant regressed in R12.)
// =====================================================================
__global__ __launch_bounds__(256) void gemm_xg_kernel(const float* __restrict__ Wih)
{
    constexpr int BK = 32, BNB = 128, LDS = BK + 8;
    __shared__ __align__(16) __half sA[2][64][LDS];
    __shared__ __align__(16) __half sB[2][BNB][LDS];

    const int tid = threadIdx.x;
    const int n0  = blockIdx.x * BNB;
    const int m0  = blockIdx.y * 64;

    const int w  = tid >> 5;
    const int wm = w >> 2, wn = w & 3;          // 2 x 4 warps, WM=32, WN=32

    wmma::fragment<wmma::accumulator, 16, 16, 16, float> acc[2][2];
#pragma unroll
    for (int i = 0; i < 2; i++)
#pragma unroll
        for (int j = 0; j < 2; j++) wmma::fill_fragment(acc[i][j], 0.0f);

    uint4 rb[2], ra;
    auto load = [&](int k0) {
#pragma unroll
        for (int p = 0; p < 2; p++) {
            int c = tid + p * 256;
            int row = c >> 2, kc = (c & 3) * 8;
            int nn = n0 + row;
            const float* s = Wih + ((size_t)(nn & 3) * V + (nn >> 2)) * V + k0 + kc;
            rb[p] = pack8(*(const float4*)s, *(const float4*)(s + 4));
        }
        {
            int row = tid >> 2, kc = (tid & 3) * 8;
            ra = *(const uint4*)(g_x16 + (size_t)(m0 + row) * V + k0 + kc);
        }
    };
    auto store = [&](int buf) {
#pragma unroll
        for (int p = 0; p < 2; p++) {
            int c = tid + p * 256;
            int row = c >> 2, kc = (c & 3) * 8;
            *(uint4*)(&sB[buf][row][kc]) = rb[p];
        }
        *(uint4*)(&sA[buf][tid >> 2][(tid & 3) * 8]) = ra;
    };

    load(0);
    store(0);
    load(BK);
    __syncthreads();

    const int niter = V / BK;   // 216
    for (int i = 0; i < niter; i++) {
        int p = i & 1;
        if (i + 1 < niter) store(p ^ 1);
        if (i + 2 < niter) load((i + 2) * BK);
#pragma unroll
        for (int kk = 0; kk < BK; kk += 16) {
            wmma::fragment<wmma::matrix_a, 16, 16, 16, __half, wmma::row_major> af[2];
            wmma::fragment<wmma::matrix_b, 16, 16, 16, __half, wmma::col_major> bf[2];
#pragma unroll
            for (int i_ = 0; i_ < 2; i_++)
                wmma::load_matrix_sync(af[i_], &sA[p][wm * 32 + i_ * 16][kk], LDS);
#pragma unroll
            for (int j_ = 0; j_ < 2; j_++)
                wmma::load_matrix_sync(bf[j_], &sB[p][wn * 32 + j_ * 16][kk], LDS);
#pragma unroll
            for (int i_ = 0; i_ < 2; i_++)
#pragma unroll
                for (int j_ = 0; j_ < 2; j_++)
                    wmma::mma_sync(acc[i_][j_], af[i_], bf[j_], acc[i_][j_]);
        }
        __syncthreads();
    }

#pragma unroll
    for (int i_ = 0; i_ < 2; i_++)
#pragma unroll
        for (int j_ = 0; j_ < 2; j_++)
            wmma::store_matrix_sync(
                g_xg + (size_t)(m0 + wm * 32 + i_ * 16) * G4 + n0 + wn * 32 + j_ * 16,
                acc[i_][j_], G4, wmma::mem_row_major);
}

// =====================================================================
// Encoder step t=0 (h0=c0=0): gates straight from interleaved xg + bias.
// =====================================================================
__global__ void step0_kernel()
{
    int idx = blockIdx.x * 256 + threadIdx.x;   // 16*V exactly
    int b = idx / V, j = idx - b * V;
    float4 x4 = *(const float4*)&g_xg[(size_t)(b * 8) * G4 + (size_t)j * 4];
    float4 bb = *(const float4*)&g_bep[j * 4];
    float i_ = sigf (x4.x + bb.x);
    float gg = tanhf(x4.z + bb.z);
    float o_ = sigf (x4.w + bb.w);
    float c  = i_ * gg;
    g_c[idx] = c;
    float h  = o_ * tanhf(c);
    g_h[idx]      = h;
    g_h16[0][idx] = __float2half(h);
}

// =====================================================================
// Shared epilogue pieces
// =====================================================================
__device__ __forceinline__ void combine8(float (*sR)[16][32], float (*sF)[64])
{
    int tid = threadIdx.x;
    for (int c = tid; c < 16 * 64; c += 256) {
        int m = c >> 6, n = c & 63;
        int f = n >> 4, cc = n & 15;
        sF[m][n] = sR[f][m][cc] + sR[f + 4][m][cc];
    }
}

__device__ __forceinline__ void enc_epilogue(float (*sF)[64], int jbase, int t,
                                             __half* __restrict__ hout)
{
    int tid = threadIdx.x;
    int b = tid >> 4, jl = tid & 15;
    int jg = jbase + jl;
    float4 pre = *(float4*)&sF[b][jl * 4];
    float4 xg4 = *(const float4*)&g_xg[(size_t)(b * 8 + t) * G4 + (size_t)jg * 4];
    float4 bb  = *(const float4*)&g_bep[jg * 4];
    float i_ = sigf (pre.x + xg4.x + bb.x);
    float f_ = sigf (pre.y + xg4.y + bb.y);
    float gg = tanhf(pre.z + xg4.z + bb.z);
    float o_ = sigf (pre.w + xg4.w + bb.w);
    int idx = b * V + jg;
    float c = f_ * g_c[idx] + i_ * gg;
    g_c[idx] = c;
    float h = o_ * tanhf(c);
    g_h[idx]  = h;
    hout[idx] = __float2half(h);
}

__device__ __forceinline__ void dec_epilogue(float (*sF)[64], int jbase,
                                             const float* __restrict__ xrev)
{
    int tid = threadIdx.x;
    int b = tid >> 4, jl = tid & 15;
    int jg = jbase + jl;
    float4 pre = *(float4*)&sF[b][jl * 4];
    float4 bb  = *(const float4*)&g_bdp[jg * 4];
    float4 ww  = *(const float4*)&g_widp[jg * 4];
    float bi = pre.x + bb.x, bf_ = pre.y + bb.y;
    float bg = pre.z + bb.z, bo = pre.w + bb.w;
    float ce = g_c[b * V + jg];
#pragma unroll
    for (int tr = 0; tr < TR; tr++) {
        float xr = xrev[b * TR + tr];
        float i_ = sigf (bi + xr * ww.x);
        float f_ = sigf (bf_ + xr * ww.y);
        float gg = tanhf(bg + xr * ww.z);
        float o_ = sigf (bo + xr * ww.w);
        float cd = f_ * ce + i_ * gg;
        size_t o = (size_t)(b * TR + tr) * V + jg;
        g_hd16[o] = __float2half(o_ * tanhf(cd));
        g_dec[o]  = 0.f;                 // pre-zero for fc_dec atomics
    }
}

// =====================================================================
// Fused recurrence step, fp16 interleaved weights (steps 2..7).
// BK=128, 3 stages, all 8 warps compute every iteration (K-half split).
// SINGLE __syncthreads per iteration: wait -> sync -> issue next stage
// (into the slot whose compute finished before this barrier) -> compute.
// =====================================================================
__global__ __launch_bounds__(256) void rec_ca_kernel(int t)
{
    constexpr int BK = 128, STAGES = 3, BNN = 64, LDS = BK + 8;
    union SM {
        struct { __half A[STAGES][16][LDS]; __half B[STAGES][BNN][LDS]; } st;
        struct { float R[8][16][32]; float F[16][64]; } ep;
    };
    __shared__ __align__(16) SM sm;

    const __half* hin  = g_h16[(t + 1) & 1];
    __half*       hout = g_h16[t & 1];

    const int tid = threadIdx.x;
    const int w   = tid >> 5;
    const int nf  = w & 3;
    const int kh  = w >> 2;
    const int n0  = blockIdx.x * BNN;
    const int niter = V / BK;   // 54

    wmma::fragment<wmma::accumulator, 16, 16, 16, float> acc;
    wmma::fill_fragment(acc, 0.0f);

    auto stage = [&](int s, int k0) {
#pragma unroll
        for (int p = 0; p < 4; p++) {               // B: 64 rows x 16 chunks
            int c = tid + p * 256;
            int row = c >> 4, kc = (c & 15) * 8;
            uint32_t d = (uint32_t)__cvta_generic_to_shared(&sm.st.B[s][row][kc]);
            const void* g = g_whh16 + (size_t)(n0 + row) * V + k0 + kc;
            asm volatile("cp.async.cg.shared.global [%0], [%1], 16;\n" :: "r"(d), "l"(g));
        }
        {                                           // A: 16 rows x 16 chunks
            int row = tid >> 4, kc = (tid & 15) * 8;
            uint32_t d = (uint32_t)__cvta_generic_to_shared(&sm.st.A[s][row][kc]);
            const void* g = hin + (size_t)row * V + k0 + kc;
            asm volatile("cp.async.cg.shared.global [%0], [%1], 16;\n" :: "r"(d), "l"(g));
        }
        asm volatile("cp.async.commit_group;\n");
    };

    int issued = 0;
    for (; issued < STAGES - 1; issued++) stage(issued, issued * BK);

    for (int i = 0; i < niter; i++) {
        // group i complete after this wait (prologue STAGES-1 + i commits so far)
        asm volatile("cp.async.wait_group %0;\n" :: "n"(STAGES - 2));
        __syncthreads();   // also: all warps finished computing slot (i-1)%STAGES
        if (issued < niter) { stage(issued % STAGES, issued * BK); issued++; }
        else                { asm volatile("cp.async.commit_group;\n"); }
        int s = i % STAGES;
        int kb = kh * 64;
#pragma unroll
        for (int kk = kb; kk < kb + 64; kk += 16) {
            wmma::fragment<wmma::matrix_a, 16, 16, 16, __half, wmma::row_major> af;
            wmma::fragment<wmma::matrix_b, 16, 16, 16, __half, wmma::col_major> bf;
            wmma::load_matrix_sync(af, &sm.st.A[s][0][kk], LDS);
            wmma::load_matrix_sync(bf, &sm.st.B[s][nf * 16][kk], LDS);
            wmma::mma_sync(acc, af, bf, acc);
        }
    }
    __syncthreads();

    wmma::store_matrix_sync(&sm.ep.R[w][0][0], acc, 32, wmma::mem_row_major);
    __syncthreads();
    combine8(sm.ep.R, sm.ep.F);
    __syncthreads();
    enc_epilogue(sm.ep.F, blockIdx.x * 16, t, hout);
}

// =====================================================================
// Fused recurrence/decoder step, fp32 weights, gate-interleave perm +
// in-register fp16 convert.  BK=64 (R11 config).  WRITEB: persist fp16.
// =====================================================================
template<bool WRITEB, bool DEC>
__global__ __launch_bounds__(256) void rec_f32_kernel(
    const float* __restrict__ W, int t, const float* __restrict__ xrev)
{
    constexpr int BK = 64, BNN = 64, LDS = BK + 8;
    union SM {
        struct { __half A[2][16][LDS]; __half B[2][BNN][LDS]; } st;
        struct { float R[8][16][32]; float F[16][64]; } ep;
    };
    __shared__ __align__(16) SM sm;

    const __half* hin  = g_h16[(t + 1) & 1];
    __half*       hout = g_h16[t & 1];

    const int tid = threadIdx.x;
    const int w   = tid >> 5;
    const int nf  = w & 3;
    const int kh  = w >> 2;
    const int n0  = blockIdx.x * BNN;
    const int niter = V / BK;   // 108

    wmma::fragment<wmma::accumulator, 16, 16, 16, float> acc;
    wmma::fill_fragment(acc, 0.0f);

    uint4 rb[2], ra;
    auto load = [&](int k0) {
#pragma unroll
        for (int p = 0; p < 2; p++) {
            int c = tid + p * 256;
            int row = c >> 3, kc = (c & 7) * 8;
            int nn = n0 + row;
            const float* s = W + ((size_t)(nn & 3) * V + (nn >> 2)) * V + k0 + kc;
            rb[p] = pack8(*(const float4*)s, *(const float4*)(s + 4));
            if constexpr (WRITEB)
                *(uint4*)(g_whh16 + (size_t)nn * V + k0 + kc) = rb[p];
        }
        if (tid < 128)
            ra = *(const uint4*)(hin + (size_t)(tid >> 3) * V + k0 + (tid & 7) * 8);
    };
    auto store = [&](int buf) {
#pragma unroll
        for (int p = 0; p < 2; p++) {
            int c = tid + p * 256;
            int row = c >> 3, kc = (c & 7) * 8;
            *(uint4*)(&sm.st.B[buf][row][kc]) = rb[p];
        }
        if (tid < 128)
            *(uint4*)(&sm.st.A[buf][tid >> 3][(tid & 7) * 8]) = ra;
    };

    load(0);
    store(0);
    load(BK);
    __syncthreads();

    for (int i = 0; i < niter; i++) {
        int p = i & 1;
        if (i + 1 < niter) store(p ^ 1);
        if (i + 2 < niter) load((i + 2) * BK);
        int kb = kh * 32;
#pragma unroll
        for (int kk = kb; kk < kb + 32; kk += 16) {
            wmma::fragment<wmma::matrix_a, 16, 16, 16, __half, wmma::row_major> af;
            wmma::fragment<wmma::matrix_b, 16, 16, 16, __half, wmma::col_major> bf;
            wmma::load_matrix_sync(af, &sm.st.A[p][0][kk], LDS);
            wmma::load_matrix_sync(bf, &sm.st.B[p][nf * 16][kk], LDS);
            wmma::mma_sync(acc, af, bf, acc);
        }
        __syncthreads();
    }

    wmma::store_matrix_sync(&sm.ep.R[w][0][0], acc, 32, wmma::mem_row_major);
    __syncthreads();
    combine8(sm.ep.R, sm.ep.F);
    __syncthreads();
    if constexpr (DEC) dec_epilogue(sm.ep.F, blockIdx.x * 16, xrev);
    else               enc_epilogue(sm.ep.F, blockIdx.x * 16, t, hout);
}

// =====================================================================
__global__ void fc_enc_kernel(const float* __restrict__ wgt,
                              const float* __restrict__ bias,
                              float* __restrict__ out)
{
    __shared__ float red[256];
    int b = blockIdx.x;
    const float* h = g_h + (size_t)b * V;
    float s = 0.0f;
    for (int k = threadIdx.x; k < V; k += 256) s = fmaf(h[k], wgt[k], s);
    red[threadIdx.x] = s;
    __syncthreads();
    for (int st = 128; st > 0; st >>= 1) {
        if (threadIdx.x < st) red[threadIdx.x] += red[threadIdx.x + st];
        __syncthreads();
    }
    if (threadIdx.x == 0) out[b] = red[0] + bias[0];
}

// =====================================================================
// fc_dec GEMM: BM=64 rows of hd, K-split 4, atomic-reduce into g_dec.
// =====================================================================
__global__ __launch_bounds__(256)
void gemm_fcdec(const __half* __restrict__ A, const float* __restrict__ Bf,
                float* __restrict__ C, int N, int klen)
{
    constexpr int BM = 64, BK = 32, BNB = 128, LDS = BK + 8;
    __shared__ __align__(16) __half sA[2][BM][LDS];
    __shared__ __align__(16) __half sB[2][BNB][LDS];
    __shared__ __align__(16) float  sC[BM][BNB + 4];

    const int tid   = threadIdx.x;
    const int n0    = blockIdx.x * BNB;
    const int kbase = blockIdx.y * klen;
    const int niter = klen / BK;

    const int w  = tid >> 5;
    const int wm = w >> 2, wn = w & 3;

    wmma::fragment<wmma::accumulator, 16, 16, 16, float> acc[2][2];
#pragma unroll
    for (int i = 0; i < 2; i++)
#pragma unroll
        for (int j = 0; j < 2; j++) wmma::fill_fragment(acc[i][j], 0.0f);

    uint4 rb[2], ra;
    auto load = [&](int k0) {
#pragma unroll
        for (int p = 0; p < 2; p++) {
            int c = tid + p * 256;
            int row = c >> 2, kc = (c & 3) * 8;
            const float* s = Bf + (size_t)(n0 + row) * V + k0 + kc;
            rb[p] = pack8(*(const float4*)s, *(const float4*)(s + 4));
        }
        ra = *(const uint4*)(A + (size_t)(tid >> 2) * V + k0 + (tid & 3) * 8);
    };
    auto store = [&](int buf) {
#pragma unroll
        for (int p = 0; p < 2; p++) {
            int c = tid + p * 256;
            int row = c >> 2, kc = (c & 3) * 8;
            *(uint4*)(&sB[buf][row][kc]) = rb[p];
        }
        *(uint4*)(&sA[buf][tid >> 2][(tid & 3) * 8]) = ra;
    };

    load(kbase);
    store(0);
    if (niter > 1) load(kbase + BK);
    __syncthreads();

    for (int i = 0; i < niter; i++) {
        int p = i & 1;
        if (i + 1 < niter) store(p ^ 1);
        if (i + 2 < niter) load(kbase + (i + 2) * BK);
#pragma unroll
        for (int kk = 0; kk < BK; kk += 16) {
            wmma::fragment<wmma::matrix_a, 16, 16, 16, __half, wmma::row_major> af[2];
            wmma::fragment<wmma::matrix_b, 16, 16, 16, __half, wmma::col_major> bf[2];
#pragma unroll
            for (int i_ = 0; i_ < 2; i_++)
                wmma::load_matrix_sync(af[i_], &sA[p][wm * 32 + i_ * 16][kk], LDS);
#pragma unroll
            for (int j_ = 0; j_ < 2; j_++)
                wmma::load_matrix_sync(bf[j_], &sB[p][wn * 32 + j_ * 16][kk], LDS);
#pragma unroll
            for (int i_ = 0; i_ < 2; i_++)
#pragma unroll
                for (int j_ = 0; j_ < 2; j_++)
                    wmma::mma_sync(acc[i_][j_], af[i_], bf[j_], acc[i_][j_]);
        }
        __syncthreads();
    }

#pragma unroll
    for (int i_ = 0; i_ < 2; i_++)
#pragma unroll
        for (int j_ = 0; j_ < 2; j_++)
            wmma::store_matrix_sync(&sC[wm * 32 + i_ * 16][wn * 32 + j_ * 16],
                                    acc[i_][j_], BNB + 4, wmma::mem_row_major);
    __syncthreads();
    for (int c = tid; c < BM * BNB; c += 256) {
        int m = c / BNB, n = c - m * BNB;
        atomicAdd(&C[(size_t)m * N + n0 + n], sC[m][n]);
    }
}

// =====================================================================
__global__ void dec_out_kernel(const float* __restrict__ fcb,
                               float* __restrict__ out)
{
    int idx = blockIdx.x * 256 + threadIdx.x;   // 64*V exactly
    int m = idx / V, n = idx - m * V;
    float val = g_dec[idx] + fcb[n];
    int b = m >> 2, tr = m & 3;
    size_t base = 16 + (size_t)(b * 12 + tr * 3) * V + n;
    out[base]         = val;
    out[base + V]     = val;
    out[base + 2 * V] = val;
}

// =====================================================================
extern "C" void kernel_launch(void* const* d_in, const int* in_sizes, int n_in,
                              void* d_out, int out_size)
{
    (void)in_sizes; (void)n_in; (void)out_size;
    const float* x        = (const float*)d_in[0];
    const float* x_rev    = (const float*)d_in[1];
    const float* W_ih_enc = (const float*)d_in[2];
    const float* W_hh_enc = (const float*)d_in[3];
    const float* b_enc    = (const float*)d_in[4];
    const float* fc_enc_w = (const float*)d_in[5];
    const float* fc_enc_b = (const float*)d_in[6];
    const float* W_ih_dec = (const float*)d_in[7];
    const float* W_hh_dec = (const float*)d_in[8];
    const float* b_dec    = (const float*)d_in[9];
    const float* fc_dec_w = (const float*)d_in[10];
    const float* fc_dec_b = (const float*)d_in[11];
    float* out = (float*)d_out;

    __half* hd16_p; float* dec_p;
    cudaGetSymbolAddress((void**)&hd16_p, g_hd16);
    cudaGetSymbolAddress((void**)&dec_p,  g_dec);

    // 0) x -> fp16 + permuted gate vectors (one launch)
    prep_conv_kernel<<<540, 256>>>(x, b_enc, b_dec, W_ih_dec);

    // 1) xg = x @ W_ih_enc^T  (BK=32, full-K, direct store, 432 blocks)
    gemm_xg_kernel<<<dim3(G4 / 128, 2), 256>>>(W_ih_enc);

    // 2) encoder step 0 -> h buf 0
    step0_kernel<<<BSZ * V / 256, 256>>>();

    // 3) step 1: fused GEMM+gates; reads buf0, writes buf1; persists fp16 W
    rec_f32_kernel<true, false><<<G4 / 64, 256>>>(W_hh_enc, 1, nullptr);

    // 4) steps 2..7: fused cp.async recurrence (single-barrier multistage)
    for (int t = 2; t < TT; t++)
        rec_ca_kernel<<<G4 / 64, 256>>>(t);

    // 5) enc_out -> d_out[0..15]
    fc_enc_kernel<<<BSZ, 256>>>(fc_enc_w, fc_enc_b, out);

    // 6) decoder: fused GEMM + all-TR gate epilogue (reads buf1; zeroes g_dec)
    rec_f32_kernel<false, true><<<G4 / 64, 256>>>(W_hh_dec, 0, x_rev);

    // 7) dec += h_d @ fc_dec_w^T (ksplit 4, atomic), bias + repeat(3) scatter
    gemm_fcdec<<<dim3(V / 128, 4), 256>>>(hd16_p, fc_dec_w, dec_p, V, V / 4);
    dec_out_kernel<<<BSZ * TR * V / 256, 256>>>(fc_dec_b, out);
}

// round 14
// speedup vs baseline: 1.0259x; 1.0028x over previous
#include <cuda_runtime.h>
#include <cuda_fp16.h>
#include <mma.h>
#include <cstddef>
#include <cstdint>

using namespace nvcuda;

#define V    6912
#define G4   27648   // 4*V
#define BSZ  16
#define TT   8
#define TR   4
#define NBLK 432     // persistent grid size

// ---------------- device scratch (no allocation allowed) ----------------
// Gate-interleaved layouts: index n' = j*4 + g  (g: 0=i,1=f,2=g,3=o)
__device__ __half g_whh16[(size_t)G4 * V];   // fp16 W_hh_enc, rows interleaved
__device__ __half g_x16 [128 * V];           // x fp16
__device__ __half g_h16 [2][BSZ * V];        // encoder h fp16, ping-pong
__device__ __half g_hd16[BSZ * TR * V];      // decoder h_d (fp16, GEMM A)
__device__ float  g_h   [BSZ * V];           // final encoder h fp32 (fc_enc)
__device__ float  g_xg  [128 * G4];          // xg, cols interleaved
__device__ float  g_dec [BSZ * TR * V];      // fc_dec accumulator (atomic)
__device__ float  g_bep [G4];                // b_enc permuted
__device__ float  g_bdp [G4];                // b_dec permuted
__device__ float  g_widp[G4];                // W_ih_dec permuted
__device__ unsigned g_bar;                   // persistent-kernel barrier counter

__device__ __forceinline__ float sigf(float x) { return 1.0f / (1.0f + expf(-x)); }

__device__ __forceinline__ uint4 pack8(float4 a, float4 b)
{
    __half2 h0 = __floats2half2_rn(a.x, a.y);
    __half2 h1 = __floats2half2_rn(a.z, a.w);
    __half2 h2 = __floats2half2_rn(b.x, b.y);
    __half2 h3 = __floats2half2_rn(b.z, b.w);
    uint4 u;
    u.x = *reinterpret_cast<unsigned*>(&h0);
    u.y = *reinterpret_cast<unsigned*>(&h1);
    u.z = *reinterpret_cast<unsigned*>(&h2);
    u.w = *reinterpret_cast<unsigned*>(&h3);
    return u;
}

// =====================================================================
// Combined prologue: blocks [0,432): x -> fp16; [432,540): permute b/W;
// also resets the grid-barrier counter (every graph replay).
// =====================================================================
__global__ void prep_conv_kernel(const float* __restrict__ x,
                                 const float* __restrict__ be,
                                 const float* __restrict__ bd,
                                 const float* __restrict__ wid)
{
    if (blockIdx.x == 0 && threadIdx.x == 0) g_bar = 0u;
    int bx = blockIdx.x;
    if (bx < 432) {
        int idx = bx * 256 + threadIdx.x;           // 432*256 = 128*V/8
        const float4* s = (const float4*)x + (size_t)idx * 2;
        ((uint4*)g_x16)[idx] = pack8(s[0], s[1]);
    } else {
        int idx = (bx - 432) * 256 + threadIdx.x;   // 108*256 = G4
        int src = (idx & 3) * V + (idx >> 2);
        g_bep[idx]  = be[src];
        g_bdp[idx]  = bd[src];
        g_widp[idx] = wid[src];
    }
}

// =====================================================================
// xg GEMM: BM=64 (grid.y = m-half), BN=128, BK=32, full K, direct store.
// =====================================================================
__global__ __launch_bounds__(256) void gemm_xg_kernel(const float* __restrict__ Wih)
{
    constexpr int BK = 32, BNB = 128, LDS = BK + 8;
    __shared__ __align__(16) __half sA[2][64][LDS];
    __shared__ __align__(16) __half sB[2][BNB][LDS];

    const int tid = threadIdx.x;
    const int n0  = blockIdx.x * BNB;
    const int m0  = blockIdx.y * 64;

    const int w  = tid >> 5;
    const int wm = w >> 2, wn = w & 3;

    wmma::fragment<wmma::accumulator, 16, 16, 16, float> acc[2][2];
#pragma unroll
    for (int i = 0; i < 2; i++)
#pragma unroll
        for (int j = 0; j < 2; j++) wmma::fill_fragment(acc[i][j], 0.0f);

    uint4 rb[2], ra;
    auto load = [&](int k0) {
#pragma unroll
        for (int p = 0; p < 2; p++) {
            int c = tid + p * 256;
            int row = c >> 2, kc = (c & 3) * 8;
            int nn = n0 + row;
            const float* s = Wih + ((size_t)(nn & 3) * V + (nn >> 2)) * V + k0 + kc;
            rb[p] = pack8(*(const float4*)s, *(const float4*)(s + 4));
        }
        {
            int row = tid >> 2, kc = (tid & 3) * 8;
            ra = *(const uint4*)(g_x16 + (size_t)(m0 + row) * V + k0 + kc);
        }
    };
    auto store = [&](int buf) {
#pragma unroll
        for (int p = 0; p < 2; p++) {
            int c = tid + p * 256;
            int row = c >> 2, kc = (c & 3) * 8;
            *(uint4*)(&sB[buf][row][kc]) = rb[p];
        }
        *(uint4*)(&sA[buf][tid >> 2][(tid & 3) * 8]) = ra;
    };

    load(0);
    store(0);
    load(BK);
    __syncthreads();

    const int niter = V / BK;   // 216
    for (int i = 0; i < niter; i++) {
        int p = i & 1;
        if (i + 1 < niter) store(p ^ 1);
        if (i + 2 < niter) load((i + 2) * BK);
#pragma unroll
        for (int kk = 0; kk < BK; kk += 16) {
            wmma::fragment<wmma::matrix_a, 16, 16, 16, __half, wmma::row_major> af[2];
            wmma::fragment<wmma::matrix_b, 16, 16, 16, __half, wmma::col_major> bf[2];
#pragma unroll
            for (int i_ = 0; i_ < 2; i_++)
                wmma::load_matrix_sync(af[i_], &sA[p][wm * 32 + i_ * 16][kk], LDS);
#pragma unroll
            for (int j_ = 0; j_ < 2; j_++)
                wmma::load_matrix_sync(bf[j_], &sB[p][wn * 32 + j_ * 16][kk], LDS);
#pragma unroll
            for (int i_ = 0; i_ < 2; i_++)
#pragma unroll
                for (int j_ = 0; j_ < 2; j_++)
                    wmma::mma_sync(acc[i_][j_], af[i_], bf[j_], acc[i_][j_]);
        }
        __syncthreads();
    }

#pragma unroll
    for (int i_ = 0; i_ < 2; i_++)
#pragma unroll
        for (int j_ = 0; j_ < 2; j_++)
            wmma::store_matrix_sync(
                g_xg + (size_t)(m0 + wm * 32 + i_ * 16) * G4 + n0 + wn * 32 + j_ * 16,
                acc[i_][j_], G4, wmma::mem_row_major);
}

// =====================================================================
// Persistent recurrence kernel: step0 + steps 1..7 + decoder in ONE
// launch with software grid barriers (grid 432, guaranteed 3 blocks/SM).
// =====================================================================
struct SMu {
    union {
        struct { __half A[3][16][136]; __half B[3][64][136]; } h;   // fp16 path
        struct { __half A[2][16][72];  __half B[2][64][72];  } f;   // fp32 path
        struct { float R[8][16][32]; float F[16][64]; } ep;          // epilogue
    };
};

__device__ __forceinline__ void grid_bar(unsigned k)
{
    __threadfence();
    __syncthreads();
    if (threadIdx.x == 0) {
        atomicAdd(&g_bar, 1u);
        volatile unsigned* p = &g_bar;
        while (*p < k * (unsigned)NBLK) { }
    }
    __syncthreads();
}

__device__ __forceinline__ void combine8(float (*sR)[16][32], float (*sF)[64])
{
    int tid = threadIdx.x;
    for (int c = tid; c < 16 * 64; c += 256) {
        int m = c >> 6, n = c & 63;
        int f = n >> 4, cc = n & 15;
        sF[m][n] = sR[f][m][cc] + sR[f + 4][m][cc];
    }
}

// fp16-weight mainloop (BK=128, 3-stage cp.async) -> sm.ep.F
__device__ __forceinline__ void compute_f16(SMu& sm, const __half* __restrict__ hin,
                                            int n0)
{
    constexpr int BK = 128, STAGES = 3, LDS = 136;
    const int tid = threadIdx.x;
    const int w = tid >> 5, nf = w & 3, kh = w >> 2;
    const int niter = V / BK;   // 54

    wmma::fragment<wmma::accumulator, 16, 16, 16, float> acc;
    wmma::fill_fragment(acc, 0.0f);

    auto stage = [&](int s, int k0) {
#pragma unroll
        for (int p = 0; p < 4; p++) {
            int c = tid + p * 256;
            int row = c >> 4, kc = (c & 15) * 8;
            uint32_t d = (uint32_t)__cvta_generic_to_shared(&sm.h.B[s][row][kc]);
            const void* g = g_whh16 + (size_t)(n0 + row) * V + k0 + kc;
            asm volatile("cp.async.cg.shared.global [%0], [%1], 16;\n" :: "r"(d), "l"(g));
        }
        {
            int row = tid >> 4, kc = (tid & 15) * 8;
            uint32_t d = (uint32_t)__cvta_generic_to_shared(&sm.h.A[s][row][kc]);
            const void* g = hin + (size_t)row * V + k0 + kc;
            asm volatile("cp.async.cg.shared.global [%0], [%1], 16;\n" :: "r"(d), "l"(g));
        }
        asm volatile("cp.async.commit_group;\n");
    };

    int issued = 0;
    for (; issued < STAGES - 1; issued++) stage(issued, issued * BK);

    for (int i = 0; i < niter; i++) {
        asm volatile("cp.async.wait_group %0;\n" :: "n"(STAGES - 2));
        __syncthreads();
        if (issued < niter) { stage(issued % STAGES, issued * BK); issued++; }
        else                { asm volatile("cp.async.commit_group;\n"); }
        int s = i % STAGES;
        int kb = kh * 64;
#pragma unroll
        for (int kk = kb; kk < kb + 64; kk += 16) {
            wmma::fragment<wmma::matrix_a, 16, 16, 16, __half, wmma::row_major> af;
            wmma::fragment<wmma::matrix_b, 16, 16, 16, __half, wmma::col_major> bf;
            wmma::load_matrix_sync(af, &sm.h.A[s][0][kk], LDS);
            wmma::load_matrix_sync(bf, &sm.h.B[s][nf * 16][kk], LDS);
            wmma::mma_sync(acc, af, bf, acc);
        }
    }
    asm volatile("cp.async.wait_group 0;\n");
    __syncthreads();
    wmma::store_matrix_sync(&sm.ep.R[w][0][0], acc, 32, wmma::mem_row_major);
    __syncthreads();
    combine8(sm.ep.R, sm.ep.F);
    __syncthreads();
}

// fp32-weight mainloop (BK=64, reg-staged, perm + convert) -> sm.ep.F
template<bool WRITEB>
__device__ __forceinline__ void compute_f32(SMu& sm, const float* __restrict__ W,
                                            const __half* __restrict__ hin, int n0)
{
    constexpr int BK = 64, LDS = 72;
    const int tid = threadIdx.x;
    const int w = tid >> 5, nf = w & 3, kh = w >> 2;
    const int niter = V / BK;   // 108

    wmma::fragment<wmma::accumulator, 16, 16, 16, float> acc;
    wmma::fill_fragment(acc, 0.0f);

    uint4 rb[2], ra;
    auto load = [&](int k0) {
#pragma unroll
        for (int p = 0; p < 2; p++) {
            int c = tid + p * 256;
            int row = c >> 3, kc = (c & 7) * 8;
            int nn = n0 + row;
            const float* s = W + ((size_t)(nn & 3) * V + (nn >> 2)) * V + k0 + kc;
            rb[p] = pack8(*(const float4*)s, *(const float4*)(s + 4));
            if constexpr (WRITEB)
                *(uint4*)(g_whh16 + (size_t)nn * V + k0 + kc) = rb[p];
        }
        if (tid < 128)
            ra = *(const uint4*)(hin + (size_t)(tid >> 3) * V + k0 + (tid & 7) * 8);
    };
    auto store = [&](int buf) {
#pragma unroll
        for (int p = 0; p < 2; p++) {
            int c = tid + p * 256;
            int row = c >> 3, kc = (c & 7) * 8;
            *(uint4*)(&sm.f.B[buf][row][kc]) = rb[p];
        }
        if (tid < 128)
            *(uint4*)(&sm.f.A[buf][tid >> 3][(tid & 7) * 8]) = ra;
    };

    load(0);
    store(0);
    load(BK);
    __syncthreads();

    for (int i = 0; i < niter; i++) {
        int p = i & 1;
        if (i + 1 < niter) store(p ^ 1);
        if (i + 2 < niter) load((i + 2) * BK);
        int kb = kh * 32;
#pragma unroll
        for (int kk = kb; kk < kb + 32; kk += 16) {
            wmma::fragment<wmma::matrix_a, 16, 16, 16, __half, wmma::row_major> af;
            wmma::fragment<wmma::matrix_b, 16, 16, 16, __half, wmma::col_major> bf;
            wmma::load_matrix_sync(af, &sm.f.A[p][0][kk], LDS);
            wmma::load_matrix_sync(bf, &sm.f.B[p][nf * 16][kk], LDS);
            wmma::mma_sync(acc, af, bf, acc);
        }
        __syncthreads();
    }

    wmma::store_matrix_sync(&sm.ep.R[w][0][0], acc, 32, wmma::mem_row_major);
    __syncthreads();
    combine8(sm.ep.R, sm.ep.F);
    __syncthreads();
}

__global__ __launch_bounds__(256, 3) void persist_kernel(
    const float* __restrict__ Whh_enc, const float* __restrict__ Whh_dec,
    const float* __restrict__ xrev)
{
    __shared__ __align__(16) SMu sm;

    const int tid   = threadIdx.x;
    const int n0    = blockIdx.x * 64;
    const int jbase = blockIdx.x * 16;
    const int eb  = tid >> 4, ejl = tid & 15;
    const int ejg = jbase + ejl;
    const int eidx = eb * V + ejg;

    unsigned nb = 0;
    float c_reg;

    // ---- step 0: h0 from xg (h=c=0) ----
    {
        float4 x4 = *(const float4*)&g_xg[(size_t)(eb * 8) * G4 + (size_t)ejg * 4];
        float4 bb = *(const float4*)&g_bep[ejg * 4];
        float i_ = sigf (x4.x + bb.x);
        float gg = tanhf(x4.z + bb.z);
        float o_ = sigf (x4.w + bb.w);
        c_reg = i_ * gg;
        g_h16[0][eidx] = __float2half(o_ * tanhf(c_reg));
    }
    grid_bar(++nb);

    // ---- steps 1..7 ----
    for (int t = 1; t < TT; t++) {
        if (t == 1) compute_f32<true>(sm, Whh_enc, g_h16[0], n0);
        else        compute_f16(sm, g_h16[(t + 1) & 1], n0);

        // enc epilogue (c in register)
        {
            float4 pre = *(float4*)&sm.ep.F[eb][ejl * 4];
            float4 xg4 = *(const float4*)&g_xg[(size_t)(eb * 8 + t) * G4 + (size_t)ejg * 4];
            float4 bb  = *(const float4*)&g_bep[ejg * 4];
            float i_ = sigf (pre.x + xg4.x + bb.x);
            float f_ = sigf (pre.y + xg4.y + bb.y);
            float gg = tanhf(pre.z + xg4.z + bb.z);
            float o_ = sigf (pre.w + xg4.w + bb.w);
            c_reg = f_ * c_reg + i_ * gg;
            float h = o_ * tanhf(c_reg);
            g_h16[t & 1][eidx] = __float2half(h);
            if (t == TT - 1) g_h[eidx] = h;
        }
        grid_bar(++nb);
    }

    // ---- decoder (reads h7 = buf 1) ----
    compute_f32<false>(sm, Whh_dec, g_h16[1], n0);
    {
        float4 pre = *(float4*)&sm.ep.F[eb][ejl * 4];
        float4 bb  = *(const float4*)&g_bdp[ejg * 4];
        float4 ww  = *(const float4*)&g_widp[ejg * 4];
        float bi = pre.x + bb.x, bf_ = pre.y + bb.y;
        float bg = pre.z + bb.z, bo = pre.w + bb.w;
#pragma unroll
        for (int tr = 0; tr < TR; tr++) {
            float xr = xrev[eb * TR + tr];
            float i_ = sigf (bi + xr * ww.x);
            float f_ = sigf (bf_ + xr * ww.y);
            float gg = tanhf(bg + xr * ww.z);
            float o_ = sigf (bo + xr * ww.w);
            float cd = f_ * c_reg + i_ * gg;
            size_t o = (size_t)(eb * TR + tr) * V + ejg;
            g_hd16[o] = __float2half(o_ * tanhf(cd));
            g_dec[o]  = 0.f;                 // pre-zero for fc_dec atomics
        }
    }
}

// =====================================================================
__global__ void fc_enc_kernel(const float* __restrict__ wgt,
                              const float* __restrict__ bias,
                              float* __restrict__ out)
{
    __shared__ float red[256];
    int b = blockIdx.x;
    const float* h = g_h + (size_t)b * V;
    float s = 0.0f;
    for (int k = threadIdx.x; k < V; k += 256) s = fmaf(h[k], wgt[k], s);
    red[threadIdx.x] = s;
    __syncthreads();
    for (int st = 128; st > 0; st >>= 1) {
        if (threadIdx.x < st) red[threadIdx.x] += red[threadIdx.x + st];
        __syncthreads();
    }
    if (threadIdx.x == 0) out[b] = red[0] + bias[0];
}

// =====================================================================
// fc_dec GEMM: BM=64 rows of hd, K-split 4, atomic-reduce into g_dec.
// =====================================================================
__global__ __launch_bounds__(256)
void gemm_fcdec(const __half* __restrict__ A, const float* __restrict__ Bf,
                float* __restrict__ C, int N, int klen)
{
    constexpr int BM = 64, BK = 32, BNB = 128, LDS = BK + 8;
    __shared__ __align__(16) __half sA[2][BM][LDS];
    __shared__ __align__(16) __half sB[2][BNB][LDS];
    __shared__ __align__(16) float  sC[BM][BNB + 4];

    const int tid   = threadIdx.x;
    const int n0    = blockIdx.x * BNB;
    const int kbase = blockIdx.y * klen;
    const int niter = klen / BK;

    const int w  = tid >> 5;
    const int wm = w >> 2, wn = w & 3;

    wmma::fragment<wmma::accumulator, 16, 16, 16, float> acc[2][2];
#pragma unroll
    for (int i = 0; i < 2; i++)
#pragma unroll
        for (int j = 0; j < 2; j++) wmma::fill_fragment(acc[i][j], 0.0f);

    uint4 rb[2], ra;
    auto load = [&](int k0) {
#pragma unroll
        for (int p = 0; p < 2; p++) {
            int c = tid + p * 256;
            int row = c >> 2, kc = (c & 3) * 8;
            const float* s = Bf + (size_t)(n0 + row) * V + k0 + kc;
            rb[p] = pack8(*(const float4*)s, *(const float4*)(s + 4));
        }
        ra = *(const uint4*)(A + (size_t)(tid >> 2) * V + k0 + (tid & 3) * 8);
    };
    auto store = [&](int buf) {
#pragma unroll
        for (int p = 0; p < 2; p++) {
            int c = tid + p * 256;
            int row = c >> 2, kc = (c & 3) * 8;
            *(uint4*)(&sB[buf][row][kc]) = rb[p];
        }
        *(uint4*)(&sA[buf][tid >> 2][(tid & 3) * 8]) = ra;
    };

    load(kbase);
    store(0);
    if (niter > 1) load(kbase + BK);
    __syncthreads();

    for (int i = 0; i < niter; i++) {
        int p = i & 1;
        if (i + 1 < niter) store(p ^ 1);
        if (i + 2 < niter) load(kbase + (i + 2) * BK);
#pragma unroll
        for (int kk = 0; kk < BK; kk += 16) {
            wmma::fragment<wmma::matrix_a, 16, 16, 16, __half, wmma::row_major> af[2];
            wmma::fragment<wmma::matrix_b, 16, 16, 16, __half, wmma::col_major> bf[2];
#pragma unroll
            for (int i_ = 0; i_ < 2; i_++)
                wmma::load_matrix_sync(af[i_], &sA[p][wm * 32 + i_ * 16][kk], LDS);
#pragma unroll
            for (int j_ = 0; j_ < 2; j_++)
                wmma::load_matrix_sync(bf[j_], &sB[p][wn * 32 + j_ * 16][kk], LDS);
#pragma unroll
            for (int i_ = 0; i_ < 2; i_++)
#pragma unroll
                for (int j_ = 0; j_ < 2; j_++)
                    wmma::mma_sync(acc[i_][j_], af[i_], bf[j_], acc[i_][j_]);
        }
        __syncthreads();
    }

#pragma unroll
    for (int i_ = 0; i_ < 2; i_++)
#pragma unroll
        for (int j_ = 0; j_ < 2; j_++)
            wmma::store_matrix_sync(&sC[wm * 32 + i_ * 16][wn * 32 + j_ * 16],
                                    acc[i_][j_], BNB + 4, wmma::mem_row_major);
    __syncthreads();
    for (int c = tid; c < BM * BNB; c += 256) {
        int m = c / BNB, n = c - m * BNB;
        atomicAdd(&C[(size_t)m * N + n0 + n], sC[m][n]);
    }
}

// =====================================================================
__global__ void dec_out_kernel(const float* __restrict__ fcb,
                               float* __restrict__ out)
{
    int idx = blockIdx.x * 256 + threadIdx.x;   // 64*V exactly
    int m = idx / V, n = idx - m * V;
    float val = g_dec[idx] + fcb[n];
    int b = m >> 2, tr = m & 3;
    size_t base = 16 + (size_t)(b * 12 + tr * 3) * V + n;
    out[base]         = val;
    out[base + V]     = val;
    out[base + 2 * V] = val;
}

// =====================================================================
extern "C" void kernel_launch(void* const* d_in, const int* in_sizes, int n_in,
                              void* d_out, int out_size)
{
    (void)in_sizes; (void)n_in; (void)out_size;
    const float* x        = (const float*)d_in[0];
    const float* x_rev    = (const float*)d_in[1];
    const float* W_ih_enc = (const float*)d_in[2];
    const float* W_hh_enc = (const float*)d_in[3];
    const float* b_enc    = (const float*)d_in[4];
    const float* fc_enc_w = (const float*)d_in[5];
    const float* fc_enc_b = (const float*)d_in[6];
    const float* W_ih_dec = (const float*)d_in[7];
    const float* W_hh_dec = (const float*)d_in[8];
    const float* b_dec    = (const float*)d_in[9];
    const float* fc_dec_w = (const float*)d_in[10];
    const float* fc_dec_b = (const float*)d_in[11];
    float* out = (float*)d_out;

    __half* hd16_p; float* dec_p;
    cudaGetSymbolAddress((void**)&hd16_p, g_hd16);
    cudaGetSymbolAddress((void**)&dec_p,  g_dec);

    // 0) x -> fp16 + permuted gate vectors + barrier reset (one launch)
    prep_conv_kernel<<<540, 256>>>(x, b_enc, b_dec, W_ih_dec);

    // 1) xg = x @ W_ih_enc^T  (BK=32, full-K, direct store, 432 blocks)
    gemm_xg_kernel<<<dim3(G4 / 128, 2), 256>>>(W_ih_enc);

    // 2) persistent kernel: step0 + steps 1..7 + decoder, grid barriers
    persist_kernel<<<NBLK, 256>>>(W_hh_enc, W_hh_dec, x_rev);

    // 3) enc_out -> d_out[0..15]
    fc_enc_kernel<<<BSZ, 256>>>(fc_enc_w, fc_enc_b, out);

    // 4) dec += h_d @ fc_dec_w^T (ksplit 4, atomic), bias + repeat(3) scatter
    gemm_fcdec<<<dim3(V / 128, 4), 256>>>(hd16_p, fc_dec_w, dec_p, V, V / 4);
    dec_out_kernel<<<BSZ * TR * V / 256, 256>>>(fc_dec_b, out);
}